// round 2
// baseline (speedup 1.0000x reference)
#include <cuda_runtime.h>
#include <cstdint>

#define NN   1024
#define C    512
#define EB   16384
#define BATCH 8
#define NLOC 128
#define HM   128
#define NSTEPS 10
#define SB   (BATCH*NLOC*NLOC)   /* 131072 */
#define RNG_N (NN*C)             /* 524288 */

// ---------------- scratch (no allocation allowed) ----------------
__device__ float g_T1[NN*C], g_T2[NN*C], g_TR[NN*C], g_H[NN*C];
__device__ float g_Hs[NN*C], g_Ht[NN*C], g_Rs[NN*C], g_Rt[NN*C], g_Os[NN*C], g_Ot[NN*C];
__device__ float g_Shat[SB], g_S[SB], g_BmT[SB];
__device__ float g_A[NN*HM], g_Bm[NN*HM];
__device__ int g_cnt[4*NN], g_off[4*(NN+1)], g_cur[4*NN], g_lst[4*EB];

// ---------------- threefry-2x32 (matches JAX) ----------------
__host__ __device__ inline void tf2x32(unsigned k0, unsigned k1,
                                       unsigned x0, unsigned x1,
                                       unsigned &o0, unsigned &o1) {
  unsigned ks2 = k0 ^ k1 ^ 0x1BD11BDAu;
  x0 += k0; x1 += k1;
#define TF_ROT(x,r) (((x)<<(r))|((x)>>(32-(r))))
#define TF_RND(r) { x0 += x1; x1 = TF_ROT(x1,(r)); x1 ^= x0; }
  TF_RND(13) TF_RND(15) TF_RND(26) TF_RND(6)
  x0 += k1;  x1 += ks2 + 1u;
  TF_RND(17) TF_RND(29) TF_RND(16) TF_RND(24)
  x0 += ks2; x1 += k0 + 2u;
  TF_RND(13) TF_RND(15) TF_RND(26) TF_RND(6)
  x0 += k0;  x1 += k1 + 3u;
  TF_RND(17) TF_RND(29) TF_RND(16) TF_RND(24)
  x0 += k1;  x1 += ks2 + 4u;
  TF_RND(13) TF_RND(15) TF_RND(26) TF_RND(6)
  x0 += ks2; x1 += k0 + 5u;
  o0 = x0; o1 = x1;
#undef TF_RND
#undef TF_ROT
}

// XLA's Giles erfinv (identical coefficients) + JAX uniform->normal mapping
__device__ __forceinline__ float bits_to_normal(unsigned bits) {
  float f = __uint_as_float((bits >> 9) | 0x3f800000u) - 1.0f;   // [0,1)
  const float LO = -0.99999994f;                                  // nextafter(-1,0)
  float u = fmaxf(LO, f * 2.0f + LO);                             // scale == 2.0f exactly
  float w = -log1pf(-u * u);
  float p;
  if (w < 5.0f) {
    w -= 2.5f;
    p = 2.81022636e-08f;
    p = fmaf(p, w, 3.43273939e-07f);
    p = fmaf(p, w, -3.5233877e-06f);
    p = fmaf(p, w, -4.39150654e-06f);
    p = fmaf(p, w, 0.00021858087f);
    p = fmaf(p, w, -0.00125372503f);
    p = fmaf(p, w, -0.00417768164f);
    p = fmaf(p, w, 0.246640727f);
    p = fmaf(p, w, 1.50140941f);
  } else {
    w = sqrtf(w) - 3.0f;
    p = -0.000200214257f;
    p = fmaf(p, w, 0.000100950558f);
    p = fmaf(p, w, 0.00134934322f);
    p = fmaf(p, w, -0.00367342844f);
    p = fmaf(p, w, 0.00573950773f);
    p = fmaf(p, w, -0.0076224613f);
    p = fmaf(p, w, 0.00943887047f);
    p = fmaf(p, w, 1.00167406f);
    p = fmaf(p, w, 2.83297682f);
  }
  return 1.41421356237309504880f * (p * u);
}

// JAX threefry_partitionable (default since jax 0.4.36):
// element i uses 64-bit counter (hi=0, lo=i); 32-bit bits = out0 ^ out1.
__global__ void rng_kernel(unsigned k0, unsigned k1, float* __restrict__ out) {
  unsigned i = blockIdx.x * 256u + threadIdx.x;   // < RNG_N
  unsigned o0, o1;
  tf2x32(k0, k1, 0u, i, o0, o1);
  out[i] = bits_to_normal(o0 ^ o1);
}

// ---------------- CSR build ----------------
__global__ void csr_count(const int* __restrict__ eis, const int* __restrict__ eit,
                          int* __restrict__ cnt) {
  int e = blockIdx.x * 256 + threadIdx.x;
  if (e >= EB) return;
  int ss = eis[e], sd = eis[EB + e];
  atomicAdd(&cnt[0 * NN + sd], 1);   // s, in (keyed by dst)
  atomicAdd(&cnt[1 * NN + ss], 1);   // s, out (keyed by src)
  int ts = eit[e], td = eit[EB + e];
  atomicAdd(&cnt[2 * NN + td], 1);
  atomicAdd(&cnt[3 * NN + ts], 1);
}

__global__ void csr_scan(const int* __restrict__ cnt, int* __restrict__ off,
                         int* __restrict__ cur) {
  int a = blockIdx.x, t = threadIdx.x;
  __shared__ int sm[NN];
  int v = cnt[a * NN + t];
  sm[t] = v; __syncthreads();
  for (int o = 1; o < NN; o <<= 1) {
    int u = (t >= o) ? sm[t - o] : 0;
    __syncthreads();
    sm[t] += u;
    __syncthreads();
  }
  int excl = sm[t] - v;
  off[a * (NN + 1) + t] = excl;
  cur[a * NN + t] = excl;
  if (t == NN - 1) off[a * (NN + 1) + NN] = sm[t];
}

__global__ void csr_fill(const int* __restrict__ eis, const int* __restrict__ eit,
                         int* __restrict__ cur, int* __restrict__ lst) {
  int e = blockIdx.x * 256 + threadIdx.x;
  if (e >= EB) return;
  int ss = eis[e], sd = eis[EB + e];
  int p = atomicAdd(&cur[0 * NN + sd], 1); lst[0 * EB + p] = ss;  // store src
  p = atomicAdd(&cur[1 * NN + ss], 1);     lst[1 * EB + p] = sd;  // store dst
  int ts = eit[e], td = eit[EB + e];
  p = atomicAdd(&cur[2 * NN + td], 1);     lst[2 * EB + p] = ts;
  p = atomicAdd(&cur[3 * NN + ts], 1);     lst[3 * EB + p] = td;
}

// ---------------- SGEMM: C = A[MxK] @ B[KxN] (+bias) (+beta*C) ----------------
__global__ __launch_bounds__(256)
void sgemm(const float* __restrict__ A, const float* __restrict__ B,
           float* __restrict__ Cm, int M, int N, int K,
           const float* __restrict__ bias, int beta) {
  __shared__ float As[16][64];
  __shared__ float Bs[16][64];
  int tid = threadIdx.x;
  int tx = tid & 15, ty = tid >> 4;
  int row0 = blockIdx.y * 64, col0 = blockIdx.x * 64;
  float acc[4][4] = {};
  for (int kt = 0; kt < K; kt += 16) {
#pragma unroll
    for (int l = 0; l < 4; l++) {
      int idx = tid + l * 256;
      int m = idx >> 4, k = idx & 15;
      As[k][m] = A[(row0 + m) * K + kt + k];
    }
#pragma unroll
    for (int l = 0; l < 4; l++) {
      int idx = tid + l * 256;
      int k = idx >> 6, n = idx & 63;
      Bs[k][n] = B[(kt + k) * N + col0 + n];
    }
    __syncthreads();
#pragma unroll
    for (int k = 0; k < 16; k++) {
      float a[4], b[4];
#pragma unroll
      for (int i = 0; i < 4; i++) a[i] = As[k][ty * 4 + i];
#pragma unroll
      for (int i = 0; i < 4; i++) b[i] = Bs[k][tx * 4 + i];
#pragma unroll
      for (int i = 0; i < 4; i++)
#pragma unroll
        for (int j = 0; j < 4; j++) acc[i][j] = fmaf(a[i], b[j], acc[i][j]);
    }
    __syncthreads();
  }
#pragma unroll
  for (int i = 0; i < 4; i++) {
    int r = row0 + ty * 4 + i;
#pragma unroll
    for (int j = 0; j < 4; j++) {
      int c = col0 + tx * 4 + j;
      float v = acc[i][j];
      if (bias) v += bias[c];
      if (beta) v += Cm[r * N + c];
      Cm[r * N + c] = v;
    }
  }
}

// ---------------- fused edge-mean + ReLU + LayerNorm ----------------
__global__ __launch_bounds__(256)
void agg_ln(const float* __restrict__ T1, const float* __restrict__ T2,
            const float* __restrict__ TR,
            const int* __restrict__ inoff, const int* __restrict__ inlst,
            const int* __restrict__ outoff, const int* __restrict__ outlst,
            const float* __restrict__ gamma, const float* __restrict__ beta,
            float* __restrict__ H) {
  int n = blockIdx.x, t = threadIdx.x;
  int c0 = t, c1 = t + 256;
  float a0 = TR[n * C + c0], a1 = TR[n * C + c1];
  {
    int s = inoff[n], e = inoff[n + 1];
    float s0 = 0.f, s1 = 0.f;
    for (int j = s; j < e; j++) {
      int m = inlst[j];
      s0 += T1[m * C + c0];
      s1 += T1[m * C + c1];
    }
    float inv = 1.0f / (float)max(e - s, 1);
    a0 += s0 * inv; a1 += s1 * inv;
  }
  {
    int s = outoff[n], e = outoff[n + 1];
    float s0 = 0.f, s1 = 0.f;
    for (int j = s; j < e; j++) {
      int m = outlst[j];
      s0 += T2[m * C + c0];
      s1 += T2[m * C + c1];
    }
    float inv = 1.0f / (float)max(e - s, 1);
    a0 += s0 * inv; a1 += s1 * inv;
  }
  a0 = fmaxf(a0, 0.f); a1 = fmaxf(a1, 0.f);
  __shared__ float red[256];
  __shared__ float mu_s, rstd_s;
  red[t] = a0 + a1; __syncthreads();
  for (int o = 128; o > 0; o >>= 1) { if (t < o) red[t] += red[t + o]; __syncthreads(); }
  if (t == 0) mu_s = red[0] * (1.0f / C);
  __syncthreads();
  float mu = mu_s;
  float d0 = a0 - mu, d1 = a1 - mu;
  __syncthreads();
  red[t] = d0 * d0 + d1 * d1; __syncthreads();
  for (int o = 128; o > 0; o >>= 1) { if (t < o) red[t] += red[t + o]; __syncthreads(); }
  if (t == 0) rstd_s = rsqrtf(red[0] * (1.0f / C) + 1e-5f);
  __syncthreads();
  float rstd = rstd_s;
  H[n * C + c0] = d0 * rstd * gamma[c0] + beta[c0];
  H[n * C + c1] = d1 * rstd * gamma[c1] + beta[c1];
}

// ---------------- S_hat = Hs_b @ Ht_b^T (batched) ----------------
__global__ __launch_bounds__(256)
void shat_kernel(const float* __restrict__ Hs, const float* __restrict__ Ht,
                 float* __restrict__ Shat) {
  int b = blockIdx.z, s0 = blockIdx.y * 32, t0 = blockIdx.x * 32;
  int tid = threadIdx.x, tx = tid & 15, ty = tid >> 4;
  __shared__ float sA[32][33], sBt[32][33];
  float acc[2][2] = {};
  for (int k0 = 0; k0 < C; k0 += 32) {
#pragma unroll
    for (int l = 0; l < 4; l++) {
      int idx = tid + l * 256;
      int r = idx >> 5, k = idx & 31;
      sA[r][k] = Hs[(b * NLOC + s0 + r) * C + k0 + k];
      sBt[r][k] = Ht[(b * NLOC + t0 + r) * C + k0 + k];
    }
    __syncthreads();
#pragma unroll
    for (int k = 0; k < 32; k++) {
      float a0 = sA[ty * 2][k], a1 = sA[ty * 2 + 1][k];
      float b0 = sBt[tx * 2][k], b1 = sBt[tx * 2 + 1][k];
      acc[0][0] = fmaf(a0, b0, acc[0][0]);
      acc[0][1] = fmaf(a0, b1, acc[0][1]);
      acc[1][0] = fmaf(a1, b0, acc[1][0]);
      acc[1][1] = fmaf(a1, b1, acc[1][1]);
    }
    __syncthreads();
  }
#pragma unroll
  for (int i = 0; i < 2; i++)
#pragma unroll
    for (int j = 0; j < 2; j++)
      Shat[b * (NLOC * NLOC) + (s0 + ty * 2 + i) * NLOC + (t0 + tx * 2 + j)] = acc[i][j];
}

// ---------------- row softmax over last dim 128 ----------------
__global__ void softmax_kernel(const float* __restrict__ in, float* __restrict__ out) {
  int row = blockIdx.x, t = threadIdx.x;
  __shared__ float red[128];
  float v = in[row * 128 + t];
  red[t] = v; __syncthreads();
  for (int o = 64; o > 0; o >>= 1) { if (t < o) red[t] = fmaxf(red[t], red[t + o]); __syncthreads(); }
  float mx = red[0]; __syncthreads();
  float e = expf(v - mx);
  red[t] = e; __syncthreads();
  for (int o = 64; o > 0; o >>= 1) { if (t < o) red[t] += red[t + o]; __syncthreads(); }
  out[row * 128 + t] = e / red[0];
}

// ---------------- R_t = S^T @ R_s (batched, K=128) ----------------
__global__ __launch_bounds__(256)
void rt_kernel(const float* __restrict__ S, const float* __restrict__ Rs,
               float* __restrict__ Rt) {
  int b = blockIdx.y, t0 = blockIdx.x * 16;
  int tid = threadIdx.x;
  __shared__ float sS[128][16];
#pragma unroll
  for (int l = 0; l < 8; l++) {
    int idx = tid + l * 256;
    int s = idx >> 4, tt = idx & 15;
    sS[s][tt] = S[b * (NLOC * NLOC) + s * NLOC + t0 + tt];
  }
  __syncthreads();
  int c = tid;
  float acc0[16] = {}, acc1[16] = {};
  for (int s = 0; s < NLOC; s++) {
    float r0 = Rs[(b * NLOC + s) * C + c];
    float r1 = Rs[(b * NLOC + s) * C + c + 256];
#pragma unroll
    for (int tt = 0; tt < 16; tt++) {
      float sv = sS[s][tt];
      acc0[tt] = fmaf(sv, r0, acc0[tt]);
      acc1[tt] = fmaf(sv, r1, acc1[tt]);
    }
  }
#pragma unroll
  for (int tt = 0; tt < 16; tt++) {
    Rt[(b * NLOC + t0 + tt) * C + c] = acc0[tt];
    Rt[(b * NLOC + t0 + tt) * C + c + 256] = acc1[tt];
  }
}

// ---------------- Bm [1024x128] -> BmT [b][h][j] ----------------
__global__ void transpose_bm(const float* __restrict__ Bm, float* __restrict__ BmT) {
  int idx = blockIdx.x * 256 + threadIdx.x;   // < SB
  int b = idx >> 14, r = idx & 16383, h = r >> 7, j = r & 127;
  BmT[idx] = Bm[(b * NLOC + j) * HM + h];
}

// ---------------- S_hat += sum_h relu(A[b,i,h]-BmT[b,h,j])*w2[h] + b2 ----------------
__global__ void pairwise(const float* __restrict__ A, const float* __restrict__ BmT,
                         const float* __restrict__ w2, const float* __restrict__ b2,
                         float* __restrict__ Shat) {
  int bi = blockIdx.x;              // b*128 + i
  int b = bi >> 7, j = threadIdx.x;
  __shared__ float sA[128], sw[128];
  sA[j] = A[bi * HM + j];
  sw[j] = w2[j];
  __syncthreads();
  float acc = 0.f;
  const float* Bp = BmT + b * (HM * NLOC) + j;
#pragma unroll 8
  for (int h = 0; h < HM; h++) {
    float d = sA[h] - Bp[h * NLOC];
    acc = fmaf(fmaxf(d, 0.f), sw[h], acc);
  }
  Shat[bi * NLOC + j] += acc + b2[0];
}

// ---------------- host-side GNN helper ----------------
static void run_gnn(const float* x, const float* W1, const float* W2, const float* Wr,
                    const float* rb, const float* g, const float* b,
                    const float* Fw, const float* Fb,
                    const int* inoff, const int* inlst,
                    const int* outoff, const int* outlst,
                    float* out, float* T1, float* T2, float* TR, float* H) {
  dim3 gg(C / 64, NN / 64);
  sgemm<<<gg, 256>>>(x, W1, T1, NN, C, C, nullptr, 0);
  sgemm<<<gg, 256>>>(x, W2, T2, NN, C, C, nullptr, 0);
  sgemm<<<gg, 256>>>(x, Wr, TR, NN, C, C, rb, 0);
  agg_ln<<<NN, 256>>>(T1, T2, TR, inoff, inlst, outoff, outlst, g, b, H);
  sgemm<<<gg, 256>>>(x, Fw, out, NN, C, C, Fb, 0);
  sgemm<<<gg, 256>>>(H, Fw + C * C, out, NN, C, C, nullptr, 1);
}

extern "C" void kernel_launch(void* const* d_in, const int* in_sizes, int n_in,
                              void* d_out, int out_size) {
  const float* x_s  = (const float*)d_in[0];
  const int*   ei_s = (const int*)d_in[1];
  const float* x_t  = (const float*)d_in[4];
  const int*   ei_t = (const int*)d_in[5];
  const float* e_lin1 = (const float*)d_in[8];
  const float* e_lin2 = (const float*)d_in[9];
  const float* e_rw   = (const float*)d_in[10];
  const float* e_rb   = (const float*)d_in[11];
  const float* e_g    = (const float*)d_in[12];
  const float* e_b    = (const float*)d_in[13];
  const float* e_fw   = (const float*)d_in[14];
  const float* e_fb   = (const float*)d_in[15];
  const float* c_lin1 = (const float*)d_in[16];
  const float* c_lin2 = (const float*)d_in[17];
  const float* c_rw   = (const float*)d_in[18];
  const float* c_rb   = (const float*)d_in[19];
  const float* c_g    = (const float*)d_in[20];
  const float* c_b    = (const float*)d_in[21];
  const float* c_fw   = (const float*)d_in[22];
  const float* c_fb   = (const float*)d_in[23];
  const float* m_w1   = (const float*)d_in[24];
  const float* m_b1   = (const float*)d_in[25];
  const float* m_w2   = (const float*)d_in[26];
  const float* m_b2   = (const float*)d_in[27];
  float* out = (float*)d_out;

  float *T1, *T2, *TR, *H, *Hs, *Ht, *Rs, *Rt, *Os, *Ot, *Shat, *S, *BmT, *Am, *Bm;
  int *cnt, *off, *cur, *lst;
  cudaGetSymbolAddress((void**)&T1, g_T1);
  cudaGetSymbolAddress((void**)&T2, g_T2);
  cudaGetSymbolAddress((void**)&TR, g_TR);
  cudaGetSymbolAddress((void**)&H,  g_H);
  cudaGetSymbolAddress((void**)&Hs, g_Hs);
  cudaGetSymbolAddress((void**)&Ht, g_Ht);
  cudaGetSymbolAddress((void**)&Rs, g_Rs);
  cudaGetSymbolAddress((void**)&Rt, g_Rt);
  cudaGetSymbolAddress((void**)&Os, g_Os);
  cudaGetSymbolAddress((void**)&Ot, g_Ot);
  cudaGetSymbolAddress((void**)&Shat, g_Shat);
  cudaGetSymbolAddress((void**)&S, g_S);
  cudaGetSymbolAddress((void**)&BmT, g_BmT);
  cudaGetSymbolAddress((void**)&Am, g_A);
  cudaGetSymbolAddress((void**)&Bm, g_Bm);
  cudaGetSymbolAddress((void**)&cnt, g_cnt);
  cudaGetSymbolAddress((void**)&off, g_off);
  cudaGetSymbolAddress((void**)&cur, g_cur);
  cudaGetSymbolAddress((void**)&lst, g_lst);

  // CSR build (edges fixed per call)
  cudaMemsetAsync(cnt, 0, 4 * NN * sizeof(int));
  csr_count<<<(EB + 255) / 256, 256>>>(ei_s, ei_t, cnt);
  csr_scan<<<4, 1024>>>(cnt, off, cur);
  csr_fill<<<(EB + 255) / 256, 256>>>(ei_s, ei_t, cur, lst);

  const int* s_inoff  = off + 0 * (NN + 1);
  const int* s_outoff = off + 1 * (NN + 1);
  const int* t_inoff  = off + 2 * (NN + 1);
  const int* t_outoff = off + 3 * (NN + 1);
  const int* s_inlst  = lst + 0 * EB;
  const int* s_outlst = lst + 1 * EB;
  const int* t_inlst  = lst + 2 * EB;
  const int* t_outlst = lst + 3 * EB;

  // embedding GNNs
  run_gnn(x_s, e_lin1, e_lin2, e_rw, e_rb, e_g, e_b, e_fw, e_fb,
          s_inoff, s_inlst, s_outoff, s_outlst, Hs, T1, T2, TR, H);
  run_gnn(x_t, e_lin1, e_lin2, e_rw, e_rb, e_g, e_b, e_fw, e_fb,
          t_inoff, t_inlst, t_outoff, t_outlst, Ht, T1, T2, TR, H);

  shat_kernel<<<dim3(4, 4, BATCH), 256>>>(Hs, Ht, Shat);
  softmax_kernel<<<NN, 128>>>(Shat, out);   // S_0

  for (int t = 0; t < NSTEPS; t++) {
    softmax_kernel<<<NN, 128>>>(Shat, S);
    unsigned fk0, fk1;
    tf2x32(0u, 42u, 0u, (unsigned)t, fk0, fk1);   // fold_in(key(42), t)
    rng_kernel<<<RNG_N / 256, 256>>>(fk0, fk1, Rs);
    rt_kernel<<<dim3(8, BATCH), 256>>>(S, Rs, Rt);
    run_gnn(Rs, c_lin1, c_lin2, c_rw, c_rb, c_g, c_b, c_fw, c_fb,
            s_inoff, s_inlst, s_outoff, s_outlst, Os, T1, T2, TR, H);
    run_gnn(Rt, c_lin1, c_lin2, c_rw, c_rb, c_g, c_b, c_fw, c_fb,
            t_inoff, t_inlst, t_outoff, t_outlst, Ot, T1, T2, TR, H);
    sgemm<<<dim3(HM / 64, NN / 64), 256>>>(Os, m_w1, Am, NN, HM, C, m_b1, 0);
    sgemm<<<dim3(HM / 64, NN / 64), 256>>>(Ot, m_w1, Bm, NN, HM, C, nullptr, 0);
    transpose_bm<<<SB / 256, 256>>>(Bm, BmT);
    pairwise<<<NN, 128>>>(Am, BmT, m_w2, m_b2, Shat);
  }
  softmax_kernel<<<NN, 128>>>(Shat, out + SB);   // S_L
}

// round 4
// speedup vs baseline: 1.5596x; 1.5596x over previous
#include <cuda_runtime.h>
#include <cstdint>

#define NN   1024
#define C    512
#define EB   16384
#define BATCH 8
#define NLOC 128
#define HM   128
#define NSTEPS 10
#define SB   (BATCH*NLOC*NLOC)   /* 131072 */
#define RNG_N (NN*C)             /* 524288 */

// ---------------- scratch (no allocation allowed) ----------------
__device__ float g_T[6*NN*C];                 // RelConv GEMM outs: [side*3+w]
__device__ float g_Hln[2*NN*C];               // LayerNorm outputs, per side
__device__ float g_Hs[NN*C], g_Ht[NN*C], g_Rs[NN*C], g_Rt[NN*C], g_Os[NN*C], g_Ot[NN*C];
__device__ float g_Shat[SB], g_S[SB], g_BmT[SB];
__device__ float g_A[NN*HM], g_Bm[NN*HM];
__device__ int g_cnt[4*NN], g_off[4*(NN+1)], g_cur[4*NN], g_lst[4*EB];

// ---------------- threefry-2x32 (matches JAX) ----------------
__host__ __device__ inline void tf2x32(unsigned k0, unsigned k1,
                                       unsigned x0, unsigned x1,
                                       unsigned &o0, unsigned &o1) {
  unsigned ks2 = k0 ^ k1 ^ 0x1BD11BDAu;
  x0 += k0; x1 += k1;
#define TF_ROT(x,r) (((x)<<(r))|((x)>>(32-(r))))
#define TF_RND(r) { x0 += x1; x1 = TF_ROT(x1,(r)); x1 ^= x0; }
  TF_RND(13) TF_RND(15) TF_RND(26) TF_RND(6)
  x0 += k1;  x1 += ks2 + 1u;
  TF_RND(17) TF_RND(29) TF_RND(16) TF_RND(24)
  x0 += ks2; x1 += k0 + 2u;
  TF_RND(13) TF_RND(15) TF_RND(26) TF_RND(6)
  x0 += k0;  x1 += k1 + 3u;
  TF_RND(17) TF_RND(29) TF_RND(16) TF_RND(24)
  x0 += k1;  x1 += ks2 + 4u;
  TF_RND(13) TF_RND(15) TF_RND(26) TF_RND(6)
  x0 += ks2; x1 += k0 + 5u;
  o0 = x0; o1 = x1;
#undef TF_RND
#undef TF_ROT
}

// XLA's Giles erfinv + JAX uniform->normal mapping
__device__ __forceinline__ float bits_to_normal(unsigned bits) {
  float f = __uint_as_float((bits >> 9) | 0x3f800000u) - 1.0f;   // [0,1)
  const float LO = -0.99999994f;
  float u = fmaxf(LO, f * 2.0f + LO);
  float w = -log1pf(-u * u);
  float p;
  if (w < 5.0f) {
    w -= 2.5f;
    p = 2.81022636e-08f;
    p = fmaf(p, w, 3.43273939e-07f);
    p = fmaf(p, w, -3.5233877e-06f);
    p = fmaf(p, w, -4.39150654e-06f);
    p = fmaf(p, w, 0.00021858087f);
    p = fmaf(p, w, -0.00125372503f);
    p = fmaf(p, w, -0.00417768164f);
    p = fmaf(p, w, 0.246640727f);
    p = fmaf(p, w, 1.50140941f);
  } else {
    w = sqrtf(w) - 3.0f;
    p = -0.000200214257f;
    p = fmaf(p, w, 0.000100950558f);
    p = fmaf(p, w, 0.00134934322f);
    p = fmaf(p, w, -0.00367342844f);
    p = fmaf(p, w, 0.00573950773f);
    p = fmaf(p, w, -0.0076224613f);
    p = fmaf(p, w, 0.00943887047f);
    p = fmaf(p, w, 1.00167406f);
    p = fmaf(p, w, 2.83297682f);
  }
  return 1.41421356237309504880f * (p * u);
}

// JAX threefry_partitionable: counter (0, i); bits = out0 ^ out1.
__global__ void rng_kernel(unsigned k0, unsigned k1, float* __restrict__ out) {
  unsigned i = blockIdx.x * 256u + threadIdx.x;
  unsigned o0, o1;
  tf2x32(k0, k1, 0u, i, o0, o1);
  out[i] = bits_to_normal(o0 ^ o1);
}

// ---------------- CSR build ----------------
__global__ void csr_count(const int* __restrict__ eis, const int* __restrict__ eit,
                          int* __restrict__ cnt) {
  int e = blockIdx.x * 256 + threadIdx.x;
  if (e >= EB) return;
  int ss = eis[e], sd = eis[EB + e];
  atomicAdd(&cnt[0 * NN + sd], 1);
  atomicAdd(&cnt[1 * NN + ss], 1);
  int ts = eit[e], td = eit[EB + e];
  atomicAdd(&cnt[2 * NN + td], 1);
  atomicAdd(&cnt[3 * NN + ts], 1);
}

__global__ void csr_scan(const int* __restrict__ cnt, int* __restrict__ off,
                         int* __restrict__ cur) {
  int a = blockIdx.x, t = threadIdx.x;
  __shared__ int sm[NN];
  int v = cnt[a * NN + t];
  sm[t] = v; __syncthreads();
  for (int o = 1; o < NN; o <<= 1) {
    int u = (t >= o) ? sm[t - o] : 0;
    __syncthreads();
    sm[t] += u;
    __syncthreads();
  }
  int excl = sm[t] - v;
  off[a * (NN + 1) + t] = excl;
  cur[a * NN + t] = excl;
  if (t == NN - 1) off[a * (NN + 1) + NN] = sm[t];
}

__global__ void csr_fill(const int* __restrict__ eis, const int* __restrict__ eit,
                         int* __restrict__ cur, int* __restrict__ lst) {
  int e = blockIdx.x * 256 + threadIdx.x;
  if (e >= EB) return;
  int ss = eis[e], sd = eis[EB + e];
  int p = atomicAdd(&cur[0 * NN + sd], 1); lst[0 * EB + p] = ss;
  p = atomicAdd(&cur[1 * NN + ss], 1);     lst[1 * EB + p] = sd;
  int ts = eit[e], td = eit[EB + e];
  p = atomicAdd(&cur[2 * NN + td], 1);     lst[2 * EB + p] = ts;
  p = atomicAdd(&cur[3 * NN + ts], 1);     lst[3 * EB + p] = td;
}

// ---------------- 3xTF32 tensor-core GEMM ----------------
struct P6 {
  const float* A[6];     // low half of A rows (stride 512)
  const float* Ah[6];    // high half (k>=512) for virtual concat; else unused
  const float* B[6];     // K x N row-major
  float*       Cc[6];    // M x N out
  const float* bias[6];  // length N or null
};

__device__ __forceinline__ float f2tf(float x) {
  unsigned r;
  asm("cvt.rna.tf32.f32 %0, %1;" : "=r"(r) : "f"(x));
  return __uint_as_float(r);
}

__device__ __forceinline__ void mma8(float* d, const unsigned* a, const unsigned* b) {
  asm volatile(
    "mma.sync.aligned.m16n8k8.row.col.f32.tf32.tf32.f32 "
    "{%0,%1,%2,%3}, {%4,%5,%6,%7}, {%8,%9}, {%0,%1,%2,%3};\n"
    : "+f"(d[0]), "+f"(d[1]), "+f"(d[2]), "+f"(d[3])
    : "r"(a[0]), "r"(a[1]), "r"(a[2]), "r"(a[3]), "r"(b[0]), "r"(b[1]));
}

// A rows have stride 512; virtual-concat selects Ah for k>=512. BK=8. 256 threads.
template<int BM, int BN>
__global__ __launch_bounds__(256) void gemm_3xtf32(P6 p, int Nn, int K) {
  const int tid = threadIdx.x;
  const int z = blockIdx.z;
  const float* __restrict__ A  = p.A[z];
  const float* __restrict__ Ahp = p.Ah[z];
  const float* __restrict__ B  = p.B[z];
  float* __restrict__ Cm = p.Cc[z];
  const float* __restrict__ bias = p.bias[z];
  const int row0 = blockIdx.y * BM, col0 = blockIdx.x * BN;

  constexpr int PAD = 4;
  __shared__ float Ahs[2][8][BM + PAD], Als[2][8][BM + PAD];
  __shared__ float Bhs[2][8][BN + PAD], Bls[2][8][BN + PAD];

  const int lane = tid & 31;
  const int wid = tid >> 5;
  const int gid = lane >> 2, tg = lane & 3;
  const int wr = wid >> 2, wc = wid & 3;         // 2 x 4 warps
  constexpr int WM = BM / 2, WN = BN / 4;
  constexpr int MI = WM / 16, NI = WN / 8;
  constexpr int NA4 = BM * 2;                    // float4 loads for A tile
  constexpr int NB4 = BN * 2;                    // float4 loads for B tile
  constexpr int LA = (NA4 + 255) / 256;
  constexpr int LB = (NB4 + 255) / 256;

  float acc[MI][NI][4];
#pragma unroll
  for (int i = 0; i < MI; i++)
#pragma unroll
    for (int j = 0; j < NI; j++)
#pragma unroll
      for (int q = 0; q < 4; q++) acc[i][j][q] = 0.f;

  float4 ra[LA], rb[LB];
  const int nk = K >> 3;

  auto ldg = [&](int kt) {
    const float* Ab = (kt >= 512) ? Ahp : A;
    int ko = kt & 511;
#pragma unroll
    for (int i = 0; i < LA; i++) {
      int idx = tid + i * 256;
      if (NA4 < 256 && idx >= NA4) break;
      int r = idx >> 1, c4 = idx & 1;
      ra[i] = *(const float4*)(Ab + (size_t)(row0 + r) * 512 + ko + c4 * 4);
    }
#pragma unroll
    for (int i = 0; i < LB; i++) {
      int idx = tid + i * 256;
      if (NB4 < 256 && idx >= NB4) break;
      int k = idx / (BN / 4), n4 = idx % (BN / 4);
      rb[i] = *(const float4*)(B + (size_t)(kt + k) * Nn + col0 + n4 * 4);
    }
  };

  auto sts = [&](int buf) {
#pragma unroll
    for (int i = 0; i < LA; i++) {
      int idx = tid + i * 256;
      if (NA4 < 256 && idx >= NA4) break;
      int r = idx >> 1, c4 = idx & 1;
      float v[4] = {ra[i].x, ra[i].y, ra[i].z, ra[i].w};
#pragma unroll
      for (int q = 0; q < 4; q++) {
        float hi = f2tf(v[q]);
        Ahs[buf][c4 * 4 + q][r] = hi;
        Als[buf][c4 * 4 + q][r] = f2tf(v[q] - hi);
      }
    }
#pragma unroll
    for (int i = 0; i < LB; i++) {
      int idx = tid + i * 256;
      if (NB4 < 256 && idx >= NB4) break;
      int k = idx / (BN / 4), n4 = idx % (BN / 4);
      float v[4] = {rb[i].x, rb[i].y, rb[i].z, rb[i].w};
      float h[4], l[4];
#pragma unroll
      for (int q = 0; q < 4; q++) { h[q] = f2tf(v[q]); l[q] = f2tf(v[q] - h[q]); }
      *(float4*)&Bhs[buf][k][n4 * 4] = make_float4(h[0], h[1], h[2], h[3]);
      *(float4*)&Bls[buf][k][n4 * 4] = make_float4(l[0], l[1], l[2], l[3]);
    }
  };

  auto compute = [&](int buf) {
    unsigned ah[MI][4], al[MI][4], bh[NI][2], bl[NI][2];
#pragma unroll
    for (int mi = 0; mi < MI; mi++) {
      int m = wr * WM + mi * 16 + gid;
      ah[mi][0] = __float_as_uint(Ahs[buf][tg][m]);
      ah[mi][1] = __float_as_uint(Ahs[buf][tg][m + 8]);
      ah[mi][2] = __float_as_uint(Ahs[buf][tg + 4][m]);
      ah[mi][3] = __float_as_uint(Ahs[buf][tg + 4][m + 8]);
      al[mi][0] = __float_as_uint(Als[buf][tg][m]);
      al[mi][1] = __float_as_uint(Als[buf][tg][m + 8]);
      al[mi][2] = __float_as_uint(Als[buf][tg + 4][m]);
      al[mi][3] = __float_as_uint(Als[buf][tg + 4][m + 8]);
    }
#pragma unroll
    for (int ni = 0; ni < NI; ni++) {
      int n = wc * WN + ni * 8 + gid;
      bh[ni][0] = __float_as_uint(Bhs[buf][tg][n]);
      bh[ni][1] = __float_as_uint(Bhs[buf][tg + 4][n]);
      bl[ni][0] = __float_as_uint(Bls[buf][tg][n]);
      bl[ni][1] = __float_as_uint(Bls[buf][tg + 4][n]);
    }
#pragma unroll
    for (int mi = 0; mi < MI; mi++)
#pragma unroll
      for (int ni = 0; ni < NI; ni++) {
        mma8(acc[mi][ni], ah[mi], bl[ni]);
        mma8(acc[mi][ni], al[mi], bh[ni]);
        mma8(acc[mi][ni], ah[mi], bh[ni]);
      }
  };

  ldg(0);
  sts(0);
  __syncthreads();
  for (int t = 0; t < nk; t++) {
    int buf = t & 1;
    if (t + 1 < nk) ldg((t + 1) << 3);
    compute(buf);
    if (t + 1 < nk) sts(buf ^ 1);
    __syncthreads();
  }

#pragma unroll
  for (int mi = 0; mi < MI; mi++) {
#pragma unroll
    for (int ni = 0; ni < NI; ni++) {
      int r = row0 + wr * WM + mi * 16 + gid;
      int c = col0 + wc * WN + ni * 8 + tg * 2;
      float b0 = bias ? bias[c] : 0.f;
      float b1 = bias ? bias[c + 1] : 0.f;
      Cm[(size_t)r * Nn + c]           = acc[mi][ni][0] + b0;
      Cm[(size_t)r * Nn + c + 1]       = acc[mi][ni][1] + b1;
      Cm[(size_t)(r + 8) * Nn + c]     = acc[mi][ni][2] + b0;
      Cm[(size_t)(r + 8) * Nn + c + 1] = acc[mi][ni][3] + b1;
    }
  }
}

// ---------------- fused edge-mean + ReLU + LayerNorm ----------------
__global__ __launch_bounds__(256)
void agg_ln(const float* __restrict__ T1, const float* __restrict__ T2,
            const float* __restrict__ TR,
            const int* __restrict__ inoff, const int* __restrict__ inlst,
            const int* __restrict__ outoff, const int* __restrict__ outlst,
            const float* __restrict__ gamma, const float* __restrict__ beta,
            float* __restrict__ H) {
  int n = blockIdx.x, t = threadIdx.x;
  int c0 = t, c1 = t + 256;
  float a0 = TR[n * C + c0], a1 = TR[n * C + c1];
  {
    int s = inoff[n], e = inoff[n + 1];
    float s0 = 0.f, s1 = 0.f;
    for (int j = s; j < e; j++) {
      int m = inlst[j];
      s0 += T1[m * C + c0];
      s1 += T1[m * C + c1];
    }
    float inv = 1.0f / (float)max(e - s, 1);
    a0 += s0 * inv; a1 += s1 * inv;
  }
  {
    int s = outoff[n], e = outoff[n + 1];
    float s0 = 0.f, s1 = 0.f;
    for (int j = s; j < e; j++) {
      int m = outlst[j];
      s0 += T2[m * C + c0];
      s1 += T2[m * C + c1];
    }
    float inv = 1.0f / (float)max(e - s, 1);
    a0 += s0 * inv; a1 += s1 * inv;
  }
  a0 = fmaxf(a0, 0.f); a1 = fmaxf(a1, 0.f);
  __shared__ float red[256];
  __shared__ float mu_s, rstd_s;
  red[t] = a0 + a1; __syncthreads();
  for (int o = 128; o > 0; o >>= 1) { if (t < o) red[t] += red[t + o]; __syncthreads(); }
  if (t == 0) mu_s = red[0] * (1.0f / C);
  __syncthreads();
  float mu = mu_s;
  float d0 = a0 - mu, d1 = a1 - mu;
  __syncthreads();
  red[t] = d0 * d0 + d1 * d1; __syncthreads();
  for (int o = 128; o > 0; o >>= 1) { if (t < o) red[t] += red[t + o]; __syncthreads(); }
  if (t == 0) rstd_s = rsqrtf(red[0] * (1.0f / C) + 1e-5f);
  __syncthreads();
  float rstd = rstd_s;
  H[n * C + c0] = d0 * rstd * gamma[c0] + beta[c0];
  H[n * C + c1] = d1 * rstd * gamma[c1] + beta[c1];
}

// ---------------- S_hat = Hs_b @ Ht_b^T ----------------
__global__ __launch_bounds__(256)
void shat_kernel(const float* __restrict__ Hs, const float* __restrict__ Ht,
                 float* __restrict__ Shat) {
  int b = blockIdx.z, s0 = blockIdx.y * 32, t0 = blockIdx.x * 32;
  int tid = threadIdx.x, tx = tid & 15, ty = tid >> 4;
  __shared__ float sA[32][33], sBt[32][33];
  float acc[2][2] = {};
  for (int k0 = 0; k0 < C; k0 += 32) {
#pragma unroll
    for (int l = 0; l < 4; l++) {
      int idx = tid + l * 256;
      int r = idx >> 5, k = idx & 31;
      sA[r][k] = Hs[(b * NLOC + s0 + r) * C + k0 + k];
      sBt[r][k] = Ht[(b * NLOC + t0 + r) * C + k0 + k];
    }
    __syncthreads();
#pragma unroll
    for (int k = 0; k < 32; k++) {
      float a0 = sA[ty * 2][k], a1 = sA[ty * 2 + 1][k];
      float b0 = sBt[tx * 2][k], b1 = sBt[tx * 2 + 1][k];
      acc[0][0] = fmaf(a0, b0, acc[0][0]);
      acc[0][1] = fmaf(a0, b1, acc[0][1]);
      acc[1][0] = fmaf(a1, b0, acc[1][0]);
      acc[1][1] = fmaf(a1, b1, acc[1][1]);
    }
    __syncthreads();
  }
#pragma unroll
  for (int i = 0; i < 2; i++)
#pragma unroll
    for (int j = 0; j < 2; j++)
      Shat[b * (NLOC * NLOC) + (s0 + ty * 2 + i) * NLOC + (t0 + tx * 2 + j)] = acc[i][j];
}

// ---------------- row softmax over last dim 128 ----------------
__global__ void softmax_kernel(const float* __restrict__ in, float* __restrict__ out) {
  int row = blockIdx.x, t = threadIdx.x;
  __shared__ float red[128];
  float v = in[row * 128 + t];
  red[t] = v; __syncthreads();
  for (int o = 64; o > 0; o >>= 1) { if (t < o) red[t] = fmaxf(red[t], red[t + o]); __syncthreads(); }
  float mx = red[0]; __syncthreads();
  float e = expf(v - mx);
  red[t] = e; __syncthreads();
  for (int o = 64; o > 0; o >>= 1) { if (t < o) red[t] += red[t + o]; __syncthreads(); }
  out[row * 128 + t] = e / red[0];
}

// ---------------- R_t = S^T @ R_s ----------------
__global__ __launch_bounds__(256)
void rt_kernel(const float* __restrict__ S, const float* __restrict__ Rs,
               float* __restrict__ Rt) {
  int b = blockIdx.y, t0 = blockIdx.x * 16;
  int tid = threadIdx.x;
  __shared__ float sS[128][16];
#pragma unroll
  for (int l = 0; l < 8; l++) {
    int idx = tid + l * 256;
    int s = idx >> 4, tt = idx & 15;
    sS[s][tt] = S[b * (NLOC * NLOC) + s * NLOC + t0 + tt];
  }
  __syncthreads();
  int c = tid;
  float acc0[16] = {}, acc1[16] = {};
  for (int s = 0; s < NLOC; s++) {
    float r0 = Rs[(b * NLOC + s) * C + c];
    float r1 = Rs[(b * NLOC + s) * C + c + 256];
#pragma unroll
    for (int tt = 0; tt < 16; tt++) {
      float sv = sS[s][tt];
      acc0[tt] = fmaf(sv, r0, acc0[tt]);
      acc1[tt] = fmaf(sv, r1, acc1[tt]);
    }
  }
#pragma unroll
  for (int tt = 0; tt < 16; tt++) {
    Rt[(b * NLOC + t0 + tt) * C + c] = acc0[tt];
    Rt[(b * NLOC + t0 + tt) * C + c + 256] = acc1[tt];
  }
}

// ---------------- Bm -> BmT [b][h][j] ----------------
__global__ void transpose_bm(const float* __restrict__ Bm, float* __restrict__ BmT) {
  int idx = blockIdx.x * 256 + threadIdx.x;
  int b = idx >> 14, r = idx & 16383, h = r >> 7, j = r & 127;
  BmT[idx] = Bm[(b * NLOC + j) * HM + h];
}

// ---------------- S_hat += sum_h relu(A-Bt)*w2 + b2 ----------------
__global__ void pairwise(const float* __restrict__ A, const float* __restrict__ BmT,
                         const float* __restrict__ w2, const float* __restrict__ b2,
                         float* __restrict__ Shat) {
  int bi = blockIdx.x;
  int b = bi >> 7, j = threadIdx.x;
  __shared__ float sA[128], sw[128];
  sA[j] = A[bi * HM + j];
  sw[j] = w2[j];
  __syncthreads();
  float acc = 0.f;
  const float* Bp = BmT + b * (HM * NLOC) + j;
#pragma unroll 8
  for (int h = 0; h < HM; h++) {
    float d = sA[h] - Bp[h * NLOC];
    acc = fmaf(fmaxf(d, 0.f), sw[h], acc);
  }
  Shat[bi * NLOC + j] += acc + b2[0];
}

// ---------------- host helpers ----------------
struct Ptrs {
  float *T, *Hln, *Hs, *Ht, *Rs, *Rt, *Os, *Ot, *Shat, *S, *BmT, *Am, *Bm;
  int *cnt, *off, *cur, *lst;
};

static void run_gnn_pair(const float* xs, const float* xt,
                         const float* W1, const float* W2, const float* Wr,
                         const float* rb, const float* g, const float* b,
                         const float* Fw, const float* Fb,
                         float* outS, float* outT, const Ptrs& q) {
  const int* off = q.off;
  const int* lst = q.lst;
  // 6-way RelConv GEMMs: z = side*3 + w
  P6 p3;
  for (int z = 0; z < 6; z++) {
    const float* x = (z < 3) ? xs : xt;
    int w = z % 3;
    p3.A[z] = x; p3.Ah[z] = x;
    p3.B[z] = (w == 0) ? W1 : (w == 1) ? W2 : Wr;
    p3.Cc[z] = q.T + (size_t)z * NN * C;
    p3.bias[z] = (w == 2) ? rb : nullptr;
  }
  gemm_3xtf32<128, 128><<<dim3(C / 128, NN / 128, 6), 256>>>(p3, C, C);

  agg_ln<<<NN, 256>>>(q.T + 0 * NN * C, q.T + 1 * NN * C, q.T + 2 * NN * C,
                      off + 0 * (NN + 1), lst + 0 * EB,
                      off + 1 * (NN + 1), lst + 1 * EB, g, b, q.Hln);
  agg_ln<<<NN, 256>>>(q.T + 3 * NN * C, q.T + 4 * NN * C, q.T + 5 * NN * C,
                      off + 2 * (NN + 1), lst + 2 * EB,
                      off + 3 * (NN + 1), lst + 3 * EB, g, b, q.Hln + NN * C);

  // virtual-concat GEMM: [x|H] @ Fw (K=1024)
  P6 pc;
  for (int z = 0; z < 2; z++) {
    pc.A[z] = z ? xt : xs;
    pc.Ah[z] = q.Hln + (size_t)z * NN * C;
    pc.B[z] = Fw;
    pc.Cc[z] = z ? outT : outS;
    pc.bias[z] = Fb;
  }
  for (int z = 2; z < 6; z++) { pc.A[z] = xs; pc.Ah[z] = xs; pc.B[z] = Fw; pc.Cc[z] = outS; pc.bias[z] = nullptr; }
  gemm_3xtf32<64, 128><<<dim3(C / 128, NN / 64, 2), 256>>>(pc, C, 2 * C);
}

extern "C" void kernel_launch(void* const* d_in, const int* in_sizes, int n_in,
                              void* d_out, int out_size) {
  const float* x_s  = (const float*)d_in[0];
  const int*   ei_s = (const int*)d_in[1];
  const float* x_t  = (const float*)d_in[4];
  const int*   ei_t = (const int*)d_in[5];
  const float* e_lin1 = (const float*)d_in[8];
  const float* e_lin2 = (const float*)d_in[9];
  const float* e_rw   = (const float*)d_in[10];
  const float* e_rb   = (const float*)d_in[11];
  const float* e_g    = (const float*)d_in[12];
  const float* e_b    = (const float*)d_in[13];
  const float* e_fw   = (const float*)d_in[14];
  const float* e_fb   = (const float*)d_in[15];
  const float* c_lin1 = (const float*)d_in[16];
  const float* c_lin2 = (const float*)d_in[17];
  const float* c_rw   = (const float*)d_in[18];
  const float* c_rb   = (const float*)d_in[19];
  const float* c_g    = (const float*)d_in[20];
  const float* c_b    = (const float*)d_in[21];
  const float* c_fw   = (const float*)d_in[22];
  const float* c_fb   = (const float*)d_in[23];
  const float* m_w1   = (const float*)d_in[24];
  const float* m_b1   = (const float*)d_in[25];
  const float* m_w2   = (const float*)d_in[26];
  const float* m_b2   = (const float*)d_in[27];
  float* out = (float*)d_out;

  Ptrs q;
  cudaGetSymbolAddress((void**)&q.T,   g_T);
  cudaGetSymbolAddress((void**)&q.Hln, g_Hln);
  cudaGetSymbolAddress((void**)&q.Hs,  g_Hs);
  cudaGetSymbolAddress((void**)&q.Ht,  g_Ht);
  cudaGetSymbolAddress((void**)&q.Rs,  g_Rs);
  cudaGetSymbolAddress((void**)&q.Rt,  g_Rt);
  cudaGetSymbolAddress((void**)&q.Os,  g_Os);
  cudaGetSymbolAddress((void**)&q.Ot,  g_Ot);
  cudaGetSymbolAddress((void**)&q.Shat, g_Shat);
  cudaGetSymbolAddress((void**)&q.S,   g_S);
  cudaGetSymbolAddress((void**)&q.BmT, g_BmT);
  cudaGetSymbolAddress((void**)&q.Am,  g_A);
  cudaGetSymbolAddress((void**)&q.Bm,  g_Bm);
  cudaGetSymbolAddress((void**)&q.cnt, g_cnt);
  cudaGetSymbolAddress((void**)&q.off, g_off);
  cudaGetSymbolAddress((void**)&q.cur, g_cur);
  cudaGetSymbolAddress((void**)&q.lst, g_lst);

  // CSR build
  cudaMemsetAsync(q.cnt, 0, 4 * NN * sizeof(int));
  csr_count<<<(EB + 255) / 256, 256>>>(ei_s, ei_t, q.cnt);
  csr_scan<<<4, 1024>>>(q.cnt, q.off, q.cur);
  csr_fill<<<(EB + 255) / 256, 256>>>(ei_s, ei_t, q.cur, q.lst);

  // embedding GNNs (both sides)
  run_gnn_pair(x_s, x_t, e_lin1, e_lin2, e_rw, e_rb, e_g, e_b, e_fw, e_fb,
               q.Hs, q.Ht, q);

  shat_kernel<<<dim3(4, 4, BATCH), 256>>>(q.Hs, q.Ht, q.Shat);
  softmax_kernel<<<NN, 128>>>(q.Shat, out);   // S_0

  for (int t = 0; t < NSTEPS; t++) {
    softmax_kernel<<<NN, 128>>>(q.Shat, q.S);
    unsigned fk0, fk1;
    tf2x32(0u, 42u, 0u, (unsigned)t, fk0, fk1);
    rng_kernel<<<RNG_N / 256, 256>>>(fk0, fk1, q.Rs);
    rt_kernel<<<dim3(8, BATCH), 256>>>(q.S, q.Rs, q.Rt);
    run_gnn_pair(q.Rs, q.Rt, c_lin1, c_lin2, c_rw, c_rb, c_g, c_b, c_fw, c_fb,
                 q.Os, q.Ot, q);
    // MLP GEMMs: Am = Os@w1 + b1 ; Bm = Ot@w1
    P6 pm;
    for (int z = 0; z < 6; z++) {
      pm.A[z] = (z == 1) ? q.Ot : q.Os;
      pm.Ah[z] = pm.A[z];
      pm.B[z] = m_w1;
      pm.Cc[z] = (z == 1) ? q.Bm : q.Am;
      pm.bias[z] = (z == 0) ? m_b1 : nullptr;
    }
    gemm_3xtf32<64, 128><<<dim3(HM / 128, NN / 64, 2), 256>>>(pm, HM, C);
    transpose_bm<<<SB / 256, 256>>>(q.Bm, q.BmT);
    pairwise<<<NN, 128>>>(q.Am, q.BmT, m_w2, m_b2, q.Shat);
  }
  softmax_kernel<<<NN, 128>>>(q.Shat, out + SB);   // S_L
}

// round 5
// speedup vs baseline: 1.9431x; 1.2459x over previous
#include <cuda_runtime.h>
#include <cstdint>

#define NN   1024
#define C    512
#define EB   16384
#define BATCH 8
#define NLOC 128
#define HM   128
#define NSTEPS 10
#define SB   (BATCH*NLOC*NLOC)   /* 131072 */
#define RNG_N (NN*C)             /* 524288 */

// ---------------- scratch (no allocation allowed) ----------------
__device__ float g_T[6*NN*C];                 // RelConv GEMM outs: [side*3+w]
__device__ float g_Hln[2*NN*C];               // LayerNorm outputs, per side
__device__ float g_Hs[NN*C], g_Ht[NN*C], g_Rs[NN*C], g_Rt[NN*C], g_Os[NN*C], g_Ot[NN*C];
__device__ float g_Shat[SB], g_S[SB], g_BmT[SB];
__device__ float g_A[NN*HM], g_Bm[NN*HM];
__device__ int g_cnt[4*NN], g_off[4*(NN+1)], g_cur[4*NN], g_lst[4*EB];

// ---------------- threefry-2x32 (matches JAX) ----------------
__host__ __device__ inline void tf2x32(unsigned k0, unsigned k1,
                                       unsigned x0, unsigned x1,
                                       unsigned &o0, unsigned &o1) {
  unsigned ks2 = k0 ^ k1 ^ 0x1BD11BDAu;
  x0 += k0; x1 += k1;
#define TF_ROT(x,r) (((x)<<(r))|((x)>>(32-(r))))
#define TF_RND(r) { x0 += x1; x1 = TF_ROT(x1,(r)); x1 ^= x0; }
  TF_RND(13) TF_RND(15) TF_RND(26) TF_RND(6)
  x0 += k1;  x1 += ks2 + 1u;
  TF_RND(17) TF_RND(29) TF_RND(16) TF_RND(24)
  x0 += ks2; x1 += k0 + 2u;
  TF_RND(13) TF_RND(15) TF_RND(26) TF_RND(6)
  x0 += k0;  x1 += k1 + 3u;
  TF_RND(17) TF_RND(29) TF_RND(16) TF_RND(24)
  x0 += k1;  x1 += ks2 + 4u;
  TF_RND(13) TF_RND(15) TF_RND(26) TF_RND(6)
  x0 += ks2; x1 += k0 + 5u;
  o0 = x0; o1 = x1;
#undef TF_RND
#undef TF_ROT
}

// XLA's Giles erfinv + JAX uniform->normal mapping
__device__ __forceinline__ float bits_to_normal(unsigned bits) {
  float f = __uint_as_float((bits >> 9) | 0x3f800000u) - 1.0f;   // [0,1)
  const float LO = -0.99999994f;
  float u = fmaxf(LO, f * 2.0f + LO);
  float w = -log1pf(-u * u);
  float p;
  if (w < 5.0f) {
    w -= 2.5f;
    p = 2.81022636e-08f;
    p = fmaf(p, w, 3.43273939e-07f);
    p = fmaf(p, w, -3.5233877e-06f);
    p = fmaf(p, w, -4.39150654e-06f);
    p = fmaf(p, w, 0.00021858087f);
    p = fmaf(p, w, -0.00125372503f);
    p = fmaf(p, w, -0.00417768164f);
    p = fmaf(p, w, 0.246640727f);
    p = fmaf(p, w, 1.50140941f);
  } else {
    w = sqrtf(w) - 3.0f;
    p = -0.000200214257f;
    p = fmaf(p, w, 0.000100950558f);
    p = fmaf(p, w, 0.00134934322f);
    p = fmaf(p, w, -0.00367342844f);
    p = fmaf(p, w, 0.00573950773f);
    p = fmaf(p, w, -0.0076224613f);
    p = fmaf(p, w, 0.00943887047f);
    p = fmaf(p, w, 1.00167406f);
    p = fmaf(p, w, 2.83297682f);
  }
  return 1.41421356237309504880f * (p * u);
}

// JAX threefry_partitionable: counter (0, i); bits = out0 ^ out1.
__global__ void rng_kernel(unsigned k0, unsigned k1, float* __restrict__ out) {
  unsigned i = blockIdx.x * 256u + threadIdx.x;
  unsigned o0, o1;
  tf2x32(k0, k1, 0u, i, o0, o1);
  out[i] = bits_to_normal(o0 ^ o1);
}

// ---------------- CSR build ----------------
__global__ void csr_count(const int* __restrict__ eis, const int* __restrict__ eit,
                          int* __restrict__ cnt) {
  int e = blockIdx.x * 256 + threadIdx.x;
  if (e >= EB) return;
  int ss = eis[e], sd = eis[EB + e];
  atomicAdd(&cnt[0 * NN + sd], 1);
  atomicAdd(&cnt[1 * NN + ss], 1);
  int ts = eit[e], td = eit[EB + e];
  atomicAdd(&cnt[2 * NN + td], 1);
  atomicAdd(&cnt[3 * NN + ts], 1);
}

__global__ void csr_scan(const int* __restrict__ cnt, int* __restrict__ off,
                         int* __restrict__ cur) {
  int a = blockIdx.x, t = threadIdx.x;
  __shared__ int sm[NN];
  int v = cnt[a * NN + t];
  sm[t] = v; __syncthreads();
  for (int o = 1; o < NN; o <<= 1) {
    int u = (t >= o) ? sm[t - o] : 0;
    __syncthreads();
    sm[t] += u;
    __syncthreads();
  }
  int excl = sm[t] - v;
  off[a * (NN + 1) + t] = excl;
  cur[a * NN + t] = excl;
  if (t == NN - 1) off[a * (NN + 1) + NN] = sm[t];
}

__global__ void csr_fill(const int* __restrict__ eis, const int* __restrict__ eit,
                         int* __restrict__ cur, int* __restrict__ lst) {
  int e = blockIdx.x * 256 + threadIdx.x;
  if (e >= EB) return;
  int ss = eis[e], sd = eis[EB + e];
  int p = atomicAdd(&cur[0 * NN + sd], 1); lst[0 * EB + p] = ss;
  p = atomicAdd(&cur[1 * NN + ss], 1);     lst[1 * EB + p] = sd;
  int ts = eit[e], td = eit[EB + e];
  p = atomicAdd(&cur[2 * NN + td], 1);     lst[2 * EB + p] = ts;
  p = atomicAdd(&cur[3 * NN + ts], 1);     lst[3 * EB + p] = td;
}

// ---------------- 3xTF32 tensor-core GEMM (BK=16, cp.async, reg split) ----------------
struct P6 {
  const float* A[6];     // low half of A rows (stride 512)
  const float* Ah[6];    // high half (k>=512) for virtual concat; else unused
  const float* B[6];     // K x N row-major
  float*       Cc[6];    // M x N out
  const float* bias[6];  // length N or null
};

__device__ __forceinline__ float f2tf(float x) {
  unsigned r;
  asm("cvt.rna.tf32.f32 %0, %1;" : "=r"(r) : "f"(x));
  return __uint_as_float(r);
}

__device__ __forceinline__ void mma8(float* d, const unsigned* a, const unsigned* b) {
  asm volatile(
    "mma.sync.aligned.m16n8k8.row.col.f32.tf32.tf32.f32 "
    "{%0,%1,%2,%3}, {%4,%5,%6,%7}, {%8,%9}, {%0,%1,%2,%3};\n"
    : "+f"(d[0]), "+f"(d[1]), "+f"(d[2]), "+f"(d[3])
    : "r"(a[0]), "r"(a[1]), "r"(a[2]), "r"(a[3]), "r"(b[0]), "r"(b[1]));
}

__device__ __forceinline__ void cpa4(unsigned dst, const float* src) {
  asm volatile("cp.async.ca.shared.global [%0], [%1], 4;" :: "r"(dst), "l"(src));
}
__device__ __forceinline__ void cpa16(unsigned dst, const float* src) {
  asm volatile("cp.async.cg.shared.global [%0], [%1], 16;" :: "r"(dst), "l"(src));
}
__device__ __forceinline__ void cp_commit() {
  asm volatile("cp.async.commit_group;");
}

// A rows stride 512; virtual-concat selects Ah for k>=512 (BK=16 never straddles).
template<int BM, int BN>
__global__ __launch_bounds__(256) void gemm_3xtf32(P6 p, int Nn, int K) {
  const int tid = threadIdx.x;
  const int z = blockIdx.z;
  const float* __restrict__ A  = p.A[z];
  const float* __restrict__ Ahp = p.Ah[z];
  const float* __restrict__ B  = p.B[z];
  float* __restrict__ Cm = p.Cc[z];
  const float* __restrict__ bias = p.bias[z];
  const int row0 = blockIdx.y * BM, col0 = blockIdx.x * BN;

  constexpr int PAD = 4;
  __shared__ float As[2][16][BM + PAD];   // raw fp32
  __shared__ float Bs[2][16][BN + PAD];

  const unsigned as_u = (unsigned)__cvta_generic_to_shared(&As[0][0][0]);
  const unsigned bs_u = (unsigned)__cvta_generic_to_shared(&Bs[0][0][0]);

  const int lane = tid & 31;
  const int wid = tid >> 5;
  const int gid = lane >> 2, tg = lane & 3;
  const int wr = wid >> 2, wc = wid & 3;         // 2 x 4 warps
  constexpr int WM = BM / 2, WN = BN / 4;
  constexpr int MI = WM / 16, NI = WN / 8;
  constexpr int CA = BM * 16 / 256;              // 4B cp.async per thread (A)
  constexpr int CB = BN * 16 / 1024;             // 16B cp.async per thread (B)

  float acc[MI][NI][4];
#pragma unroll
  for (int i = 0; i < MI; i++)
#pragma unroll
    for (int j = 0; j < NI; j++)
#pragma unroll
      for (int q = 0; q < 4; q++) acc[i][j][q] = 0.f;

  const int nk = K >> 4;

  auto ldg = [&](int kt, int buf) {
    const float* Ab = (kt >= 512) ? Ahp : A;
    int ko = kt & 511;
#pragma unroll
    for (int i = 0; i < CA; i++) {
      int idx = tid + i * 256;
      int k = idx & 15, m = idx >> 4;
      unsigned dst = as_u + (unsigned)(((buf * 16 + k) * (BM + PAD) + m) * 4);
      cpa4(dst, Ab + (size_t)(row0 + m) * 512 + ko + k);
    }
#pragma unroll
    for (int i = 0; i < CB; i++) {
      int idx = tid + i * 256;
      int k = idx / (BN / 4), n4 = idx % (BN / 4);
      unsigned dst = bs_u + (unsigned)(((buf * 16 + k) * (BN + PAD) + n4 * 4) * 4);
      cpa16(dst, B + (size_t)(kt + k) * Nn + col0 + n4 * 4);
    }
  };

  auto compute = [&](int buf) {
#pragma unroll
    for (int kk = 0; kk < 16; kk += 8) {
      unsigned ah[MI][4], al[MI][4], bh[NI][2], bl[NI][2];
#pragma unroll
      for (int mi = 0; mi < MI; mi++) {
        int m = wr * WM + mi * 16 + gid;
        float v0 = As[buf][kk + tg][m];
        float v1 = As[buf][kk + tg][m + 8];
        float v2 = As[buf][kk + tg + 4][m];
        float v3 = As[buf][kk + tg + 4][m + 8];
        float h0 = f2tf(v0), h1 = f2tf(v1), h2 = f2tf(v2), h3 = f2tf(v3);
        ah[mi][0] = __float_as_uint(h0); al[mi][0] = __float_as_uint(f2tf(v0 - h0));
        ah[mi][1] = __float_as_uint(h1); al[mi][1] = __float_as_uint(f2tf(v1 - h1));
        ah[mi][2] = __float_as_uint(h2); al[mi][2] = __float_as_uint(f2tf(v2 - h2));
        ah[mi][3] = __float_as_uint(h3); al[mi][3] = __float_as_uint(f2tf(v3 - h3));
      }
#pragma unroll
      for (int ni = 0; ni < NI; ni++) {
        int n = wc * WN + ni * 8 + gid;
        float u0 = Bs[buf][kk + tg][n];
        float u1 = Bs[buf][kk + tg + 4][n];
        float h0 = f2tf(u0), h1 = f2tf(u1);
        bh[ni][0] = __float_as_uint(h0); bl[ni][0] = __float_as_uint(f2tf(u0 - h0));
        bh[ni][1] = __float_as_uint(h1); bl[ni][1] = __float_as_uint(f2tf(u1 - h1));
      }
#pragma unroll
      for (int mi = 0; mi < MI; mi++)
#pragma unroll
        for (int ni = 0; ni < NI; ni++) {
          mma8(acc[mi][ni], ah[mi], bl[ni]);
          mma8(acc[mi][ni], al[mi], bh[ni]);
          mma8(acc[mi][ni], ah[mi], bh[ni]);
        }
    }
  };

  ldg(0, 0);
  cp_commit();
  for (int t = 0; t < nk; t++) {
    int buf = t & 1;
    if (t + 1 < nk) {
      ldg((t + 1) << 4, buf ^ 1);
      cp_commit();
      asm volatile("cp.async.wait_group 1;");
    } else {
      asm volatile("cp.async.wait_group 0;");
    }
    __syncthreads();
    compute(buf);
    __syncthreads();
  }

#pragma unroll
  for (int mi = 0; mi < MI; mi++) {
#pragma unroll
    for (int ni = 0; ni < NI; ni++) {
      int r = row0 + wr * WM + mi * 16 + gid;
      int c = col0 + wc * WN + ni * 8 + tg * 2;
      float b0 = bias ? bias[c] : 0.f;
      float b1 = bias ? bias[c + 1] : 0.f;
      Cm[(size_t)r * Nn + c]           = acc[mi][ni][0] + b0;
      Cm[(size_t)r * Nn + c + 1]       = acc[mi][ni][1] + b1;
      Cm[(size_t)(r + 8) * Nn + c]     = acc[mi][ni][2] + b0;
      Cm[(size_t)(r + 8) * Nn + c + 1] = acc[mi][ni][3] + b1;
    }
  }
}

// ---------------- fused edge-mean + ReLU + LayerNorm ----------------
__global__ __launch_bounds__(256)
void agg_ln(const float* __restrict__ T1, const float* __restrict__ T2,
            const float* __restrict__ TR,
            const int* __restrict__ inoff, const int* __restrict__ inlst,
            const int* __restrict__ outoff, const int* __restrict__ outlst,
            const float* __restrict__ gamma, const float* __restrict__ beta,
            float* __restrict__ H) {
  int n = blockIdx.x, t = threadIdx.x;
  int c0 = t, c1 = t + 256;
  float a0 = TR[n * C + c0], a1 = TR[n * C + c1];
  {
    int s = inoff[n], e = inoff[n + 1];
    float s0 = 0.f, s1 = 0.f;
    for (int j = s; j < e; j++) {
      int m = inlst[j];
      s0 += T1[m * C + c0];
      s1 += T1[m * C + c1];
    }
    float inv = 1.0f / (float)max(e - s, 1);
    a0 += s0 * inv; a1 += s1 * inv;
  }
  {
    int s = outoff[n], e = outoff[n + 1];
    float s0 = 0.f, s1 = 0.f;
    for (int j = s; j < e; j++) {
      int m = outlst[j];
      s0 += T2[m * C + c0];
      s1 += T2[m * C + c1];
    }
    float inv = 1.0f / (float)max(e - s, 1);
    a0 += s0 * inv; a1 += s1 * inv;
  }
  a0 = fmaxf(a0, 0.f); a1 = fmaxf(a1, 0.f);
  __shared__ float red[256];
  __shared__ float mu_s, rstd_s;
  red[t] = a0 + a1; __syncthreads();
  for (int o = 128; o > 0; o >>= 1) { if (t < o) red[t] += red[t + o]; __syncthreads(); }
  if (t == 0) mu_s = red[0] * (1.0f / C);
  __syncthreads();
  float mu = mu_s;
  float d0 = a0 - mu, d1 = a1 - mu;
  __syncthreads();
  red[t] = d0 * d0 + d1 * d1; __syncthreads();
  for (int o = 128; o > 0; o >>= 1) { if (t < o) red[t] += red[t + o]; __syncthreads(); }
  if (t == 0) rstd_s = rsqrtf(red[0] * (1.0f / C) + 1e-5f);
  __syncthreads();
  float rstd = rstd_s;
  H[n * C + c0] = d0 * rstd * gamma[c0] + beta[c0];
  H[n * C + c1] = d1 * rstd * gamma[c1] + beta[c1];
}

// ---------------- S_hat = Hs_b @ Ht_b^T ----------------
__global__ __launch_bounds__(256)
void shat_kernel(const float* __restrict__ Hs, const float* __restrict__ Ht,
                 float* __restrict__ Shat) {
  int b = blockIdx.z, s0 = blockIdx.y * 32, t0 = blockIdx.x * 32;
  int tid = threadIdx.x, tx = tid & 15, ty = tid >> 4;
  __shared__ float sA[32][33], sBt[32][33];
  float acc[2][2] = {};
  for (int k0 = 0; k0 < C; k0 += 32) {
#pragma unroll
    for (int l = 0; l < 4; l++) {
      int idx = tid + l * 256;
      int r = idx >> 5, k = idx & 31;
      sA[r][k] = Hs[(b * NLOC + s0 + r) * C + k0 + k];
      sBt[r][k] = Ht[(b * NLOC + t0 + r) * C + k0 + k];
    }
    __syncthreads();
#pragma unroll
    for (int k = 0; k < 32; k++) {
      float a0 = sA[ty * 2][k], a1 = sA[ty * 2 + 1][k];
      float b0 = sBt[tx * 2][k], b1 = sBt[tx * 2 + 1][k];
      acc[0][0] = fmaf(a0, b0, acc[0][0]);
      acc[0][1] = fmaf(a0, b1, acc[0][1]);
      acc[1][0] = fmaf(a1, b0, acc[1][0]);
      acc[1][1] = fmaf(a1, b1, acc[1][1]);
    }
    __syncthreads();
  }
#pragma unroll
  for (int i = 0; i < 2; i++)
#pragma unroll
    for (int j = 0; j < 2; j++)
      Shat[b * (NLOC * NLOC) + (s0 + ty * 2 + i) * NLOC + (t0 + tx * 2 + j)] = acc[i][j];
}

// ---------------- row softmax over last dim 128 ----------------
__global__ void softmax_kernel(const float* __restrict__ in, float* __restrict__ out) {
  int row = blockIdx.x, t = threadIdx.x;
  __shared__ float red[128];
  float v = in[row * 128 + t];
  red[t] = v; __syncthreads();
  for (int o = 64; o > 0; o >>= 1) { if (t < o) red[t] = fmaxf(red[t], red[t + o]); __syncthreads(); }
  float mx = red[0]; __syncthreads();
  float e = expf(v - mx);
  red[t] = e; __syncthreads();
  for (int o = 64; o > 0; o >>= 1) { if (t < o) red[t] += red[t + o]; __syncthreads(); }
  out[row * 128 + t] = e / red[0];
}

// ---------------- R_t = S^T @ R_s ----------------
__global__ __launch_bounds__(256)
void rt_kernel(const float* __restrict__ S, const float* __restrict__ Rs,
               float* __restrict__ Rt) {
  int b = blockIdx.y, t0 = blockIdx.x * 16;
  int tid = threadIdx.x;
  __shared__ float sS[128][16];
#pragma unroll
  for (int l = 0; l < 8; l++) {
    int idx = tid + l * 256;
    int s = idx >> 4, tt = idx & 15;
    sS[s][tt] = S[b * (NLOC * NLOC) + s * NLOC + t0 + tt];
  }
  __syncthreads();
  int c = tid;
  float acc0[16] = {}, acc1[16] = {};
  for (int s = 0; s < NLOC; s++) {
    float r0 = Rs[(b * NLOC + s) * C + c];
    float r1 = Rs[(b * NLOC + s) * C + c + 256];
#pragma unroll
    for (int tt = 0; tt < 16; tt++) {
      float sv = sS[s][tt];
      acc0[tt] = fmaf(sv, r0, acc0[tt]);
      acc1[tt] = fmaf(sv, r1, acc1[tt]);
    }
  }
#pragma unroll
  for (int tt = 0; tt < 16; tt++) {
    Rt[(b * NLOC + t0 + tt) * C + c] = acc0[tt];
    Rt[(b * NLOC + t0 + tt) * C + c + 256] = acc1[tt];
  }
}

// ---------------- Bm -> BmT [b][h][j] ----------------
__global__ void transpose_bm(const float* __restrict__ Bm, float* __restrict__ BmT) {
  int idx = blockIdx.x * 256 + threadIdx.x;
  int b = idx >> 14, r = idx & 16383, h = r >> 7, j = r & 127;
  BmT[idx] = Bm[(b * NLOC + j) * HM + h];
}

// ---------------- S_hat += sum_h relu(A-Bt)*w2 + b2 ----------------
__global__ void pairwise(const float* __restrict__ A, const float* __restrict__ BmT,
                         const float* __restrict__ w2, const float* __restrict__ b2,
                         float* __restrict__ Shat) {
  int bi = blockIdx.x;
  int b = bi >> 7, j = threadIdx.x;
  __shared__ float sA[128], sw[128];
  sA[j] = A[bi * HM + j];
  sw[j] = w2[j];
  __syncthreads();
  float acc = 0.f;
  const float* Bp = BmT + b * (HM * NLOC) + j;
#pragma unroll 8
  for (int h = 0; h < HM; h++) {
    float d = sA[h] - Bp[h * NLOC];
    acc = fmaf(fmaxf(d, 0.f), sw[h], acc);
  }
  Shat[bi * NLOC + j] += acc + b2[0];
}

// ---------------- host helpers ----------------
struct Ptrs {
  float *T, *Hln, *Hs, *Ht, *Rs, *Rt, *Os, *Ot, *Shat, *S, *BmT, *Am, *Bm;
  int *cnt, *off, *cur, *lst;
};

static void run_gnn_pair(const float* xs, const float* xt,
                         const float* W1, const float* W2, const float* Wr,
                         const float* rb, const float* g, const float* b,
                         const float* Fw, const float* Fb,
                         float* outS, float* outT, const Ptrs& q) {
  const int* off = q.off;
  const int* lst = q.lst;
  // 6-way RelConv GEMMs: z = side*3 + w
  P6 p3;
  for (int z = 0; z < 6; z++) {
    const float* x = (z < 3) ? xs : xt;
    int w = z % 3;
    p3.A[z] = x; p3.Ah[z] = x;
    p3.B[z] = (w == 0) ? W1 : (w == 1) ? W2 : Wr;
    p3.Cc[z] = q.T + (size_t)z * NN * C;
    p3.bias[z] = (w == 2) ? rb : nullptr;
  }
  gemm_3xtf32<128, 128><<<dim3(C / 128, NN / 128, 6), 256>>>(p3, C, C);

  agg_ln<<<NN, 256>>>(q.T + 0 * NN * C, q.T + 1 * NN * C, q.T + 2 * NN * C,
                      off + 0 * (NN + 1), lst + 0 * EB,
                      off + 1 * (NN + 1), lst + 1 * EB, g, b, q.Hln);
  agg_ln<<<NN, 256>>>(q.T + 3 * NN * C, q.T + 4 * NN * C, q.T + 5 * NN * C,
                      off + 2 * (NN + 1), lst + 2 * EB,
                      off + 3 * (NN + 1), lst + 3 * EB, g, b, q.Hln + NN * C);

  // virtual-concat GEMM: [x|H] @ Fw (K=1024)
  P6 pc;
  for (int z = 0; z < 2; z++) {
    pc.A[z] = z ? xt : xs;
    pc.Ah[z] = q.Hln + (size_t)z * NN * C;
    pc.B[z] = Fw;
    pc.Cc[z] = z ? outT : outS;
    pc.bias[z] = Fb;
  }
  for (int z = 2; z < 6; z++) { pc.A[z] = xs; pc.Ah[z] = xs; pc.B[z] = Fw; pc.Cc[z] = outS; pc.bias[z] = nullptr; }
  gemm_3xtf32<64, 128><<<dim3(C / 128, NN / 64, 2), 256>>>(pc, C, 2 * C);
}

extern "C" void kernel_launch(void* const* d_in, const int* in_sizes, int n_in,
                              void* d_out, int out_size) {
  const float* x_s  = (const float*)d_in[0];
  const int*   ei_s = (const int*)d_in[1];
  const float* x_t  = (const float*)d_in[4];
  const int*   ei_t = (const int*)d_in[5];
  const float* e_lin1 = (const float*)d_in[8];
  const float* e_lin2 = (const float*)d_in[9];
  const float* e_rw   = (const float*)d_in[10];
  const float* e_rb   = (const float*)d_in[11];
  const float* e_g    = (const float*)d_in[12];
  const float* e_b    = (const float*)d_in[13];
  const float* e_fw   = (const float*)d_in[14];
  const float* e_fb   = (const float*)d_in[15];
  const float* c_lin1 = (const float*)d_in[16];
  const float* c_lin2 = (const float*)d_in[17];
  const float* c_rw   = (const float*)d_in[18];
  const float* c_rb   = (const float*)d_in[19];
  const float* c_g    = (const float*)d_in[20];
  const float* c_b    = (const float*)d_in[21];
  const float* c_fw   = (const float*)d_in[22];
  const float* c_fb   = (const float*)d_in[23];
  const float* m_w1   = (const float*)d_in[24];
  const float* m_b1   = (const float*)d_in[25];
  const float* m_w2   = (const float*)d_in[26];
  const float* m_b2   = (const float*)d_in[27];
  float* out = (float*)d_out;

  Ptrs q;
  cudaGetSymbolAddress((void**)&q.T,   g_T);
  cudaGetSymbolAddress((void**)&q.Hln, g_Hln);
  cudaGetSymbolAddress((void**)&q.Hs,  g_Hs);
  cudaGetSymbolAddress((void**)&q.Ht,  g_Ht);
  cudaGetSymbolAddress((void**)&q.Rs,  g_Rs);
  cudaGetSymbolAddress((void**)&q.Rt,  g_Rt);
  cudaGetSymbolAddress((void**)&q.Os,  g_Os);
  cudaGetSymbolAddress((void**)&q.Ot,  g_Ot);
  cudaGetSymbolAddress((void**)&q.Shat, g_Shat);
  cudaGetSymbolAddress((void**)&q.S,   g_S);
  cudaGetSymbolAddress((void**)&q.BmT, g_BmT);
  cudaGetSymbolAddress((void**)&q.Am,  g_A);
  cudaGetSymbolAddress((void**)&q.Bm,  g_Bm);
  cudaGetSymbolAddress((void**)&q.cnt, g_cnt);
  cudaGetSymbolAddress((void**)&q.off, g_off);
  cudaGetSymbolAddress((void**)&q.cur, g_cur);
  cudaGetSymbolAddress((void**)&q.lst, g_lst);

  // CSR build
  cudaMemsetAsync(q.cnt, 0, 4 * NN * sizeof(int));
  csr_count<<<(EB + 255) / 256, 256>>>(ei_s, ei_t, q.cnt);
  csr_scan<<<4, 1024>>>(q.cnt, q.off, q.cur);
  csr_fill<<<(EB + 255) / 256, 256>>>(ei_s, ei_t, q.cur, q.lst);

  // embedding GNNs (both sides)
  run_gnn_pair(x_s, x_t, e_lin1, e_lin2, e_rw, e_rb, e_g, e_b, e_fw, e_fb,
               q.Hs, q.Ht, q);

  shat_kernel<<<dim3(4, 4, BATCH), 256>>>(q.Hs, q.Ht, q.Shat);
  softmax_kernel<<<NN, 128>>>(q.Shat, out);   // S_0

  for (int t = 0; t < NSTEPS; t++) {
    softmax_kernel<<<NN, 128>>>(q.Shat, q.S);
    unsigned fk0, fk1;
    tf2x32(0u, 42u, 0u, (unsigned)t, fk0, fk1);
    rng_kernel<<<RNG_N / 256, 256>>>(fk0, fk1, q.Rs);
    rt_kernel<<<dim3(8, BATCH), 256>>>(q.S, q.Rs, q.Rt);
    run_gnn_pair(q.Rs, q.Rt, c_lin1, c_lin2, c_rw, c_rb, c_g, c_b, c_fw, c_fb,
                 q.Os, q.Ot, q);
    // MLP GEMMs: Am = Os@w1 + b1 ; Bm = Ot@w1
    P6 pm;
    for (int z = 0; z < 6; z++) {
      pm.A[z] = (z == 1) ? q.Ot : q.Os;
      pm.Ah[z] = pm.A[z];
      pm.B[z] = m_w1;
      pm.Cc[z] = (z == 1) ? q.Bm : q.Am;
      pm.bias[z] = (z == 0) ? m_b1 : nullptr;
    }
    gemm_3xtf32<32, 64><<<dim3(HM / 64, NN / 32, 2), 256>>>(pm, HM, C);
    transpose_bm<<<SB / 256, 256>>>(q.Bm, q.BmT);
    pairwise<<<NN, 128>>>(q.Am, q.BmT, m_w2, m_b2, q.Shat);
  }
  softmax_kernel<<<NN, 128>>>(q.Shat, out + SB);   // S_L
}